// round 2
// baseline (speedup 1.0000x reference)
#include <cuda_runtime.h>
#include <cuda_bf16.h>

#define NN 30000
#define EE 300000
#define ET 330000         // EE + NN self loops
#define GG 128
#define IN_DIM 128
#define HID 64
#define HEADS 4
#define CH 256            // HEADS*HID
#define NC 10
#define EPS 1e-5f
#define SLOPE 0.2f

// ---------------- scratch (device globals; no allocation allowed) ----------
__device__ float g_xl[NN * CH];
__device__ float g_xr[NN * CH];
__device__ float g_h[NN * CH];
__device__ float g_agg[NN * CH];
__device__ float g_e[ET * HEADS];
__device__ unsigned g_menc[NN * HEADS];
__device__ float g_m[NN * HEADS];
__device__ float g_s[NN * HEADS];
__device__ double g_bnsum[CH];
__device__ double g_bnsq[CH];
__device__ float g_pool[GG * HID];
__device__ float g_cnt[GG];

// ---------------- helpers --------------------------------------------------
__device__ __forceinline__ unsigned fenc(float f) {
    unsigned u = __float_as_uint(f);
    return (u & 0x80000000u) ? ~u : (u | 0x80000000u);
}
__device__ __forceinline__ float fdec(unsigned u) {
    return (u & 0x80000000u) ? __uint_as_float(u & 0x7fffffffu)
                             : __uint_as_float(~u);
}
__device__ __forceinline__ float leaky(float x) {
    return x > 0.f ? x : SLOPE * x;
}
__device__ __forceinline__ void edge_sd(const int* __restrict__ ei, int e,
                                        int& s, int& d) {
    if (e < EE) { s = ei[e]; d = ei[EE + e]; }
    else        { s = e - EE; d = e - EE; }
}

// ---------------- GEMM: C[N x 256] = A[N x K] @ W[K x 256] -----------------
#define BM 64
#define BN 64
#define BK 16
__global__ void gemm_kernel(const float* __restrict__ xin,
                            const float* __restrict__ W,
                            int K, int a_sel, int c_sel) {
    __shared__ float As[BM][BK + 1];
    __shared__ float Bs[BK][BN];
    const float* A = a_sel ? g_h : xin;
    float* C = c_sel ? g_xr : g_xl;

    int bm = blockIdx.y * BM;
    int bn = blockIdx.x * BN;
    int tx = threadIdx.x & 15;
    int ty = threadIdx.x >> 4;

    float acc[4][4];
#pragma unroll
    for (int i = 0; i < 4; i++)
#pragma unroll
        for (int j = 0; j < 4; j++) acc[i][j] = 0.f;

    for (int k0 = 0; k0 < K; k0 += BK) {
        // A tile: 64 x 16, consecutive threads load consecutive k
        for (int i = threadIdx.x; i < BM * BK; i += 256) {
            int m = i >> 4, kk = i & 15;
            int row = bm + m;
            As[m][kk] = (row < NN) ? A[row * K + k0 + kk] : 0.f;
        }
        // B tile: 16 x 64, consecutive threads load consecutive n
        for (int i = threadIdx.x; i < BK * BN; i += 256) {
            int kk = i >> 6, n = i & 63;
            Bs[kk][n] = W[(k0 + kk) * CH + bn + n];
        }
        __syncthreads();
#pragma unroll
        for (int kk = 0; kk < BK; kk++) {
            float ra[4], rb[4];
#pragma unroll
            for (int i = 0; i < 4; i++) ra[i] = As[ty * 4 + i][kk];
#pragma unroll
            for (int j = 0; j < 4; j++) rb[j] = Bs[kk][tx * 4 + j];
#pragma unroll
            for (int i = 0; i < 4; i++)
#pragma unroll
                for (int j = 0; j < 4; j++) acc[i][j] += ra[i] * rb[j];
        }
        __syncthreads();
    }
#pragma unroll
    for (int i = 0; i < 4; i++) {
        int row = bm + ty * 4 + i;
        if (row < NN) {
#pragma unroll
            for (int j = 0; j < 4; j++)
                C[row * CH + bn + tx * 4 + j] = acc[i][j];
        }
    }
}

// ---------------- clears ---------------------------------------------------
__global__ void clear_edge_kernel() {
    int tid = blockIdx.x * blockDim.x + threadIdx.x;
    if (tid < NN * CH) g_agg[tid] = 0.f;
    if (tid < NN * HEADS) { g_menc[tid] = 0u; g_s[tid] = 0.f; }
}
__global__ void clear_bn_kernel() {
    int t = threadIdx.x;
    if (t < CH) { g_bnsum[t] = 0.0; g_bnsq[t] = 0.0; }
}
__global__ void clear_pool_kernel() {
    int tid = blockIdx.x * blockDim.x + threadIdx.x;
    if (tid < GG * HID) g_pool[tid] = 0.f;
    if (tid < GG) g_cnt[tid] = 0.f;
}

// ---------------- edge stage 1: attention logits + segment max -------------
__global__ void edge_e_kernel(const int* __restrict__ ei,
                              const float* __restrict__ att) {
    int edge = blockIdx.x * 8 + (threadIdx.x >> 5);
    if (edge >= ET) return;
    int lane = threadIdx.x & 31;
    int s, d;
    edge_sd(ei, edge, s, d);
    const float* xlp = g_xl + s * CH;
    const float* xrp = g_xr + d * CH;
#pragma unroll
    for (int h = 0; h < HEADS; h++) {
        int base = h * HID;
        float v = leaky(xlp[base + lane] + xrp[base + lane]) * att[base + lane]
                + leaky(xlp[base + lane + 32] + xrp[base + lane + 32]) * att[base + lane + 32];
#pragma unroll
        for (int off = 16; off; off >>= 1)
            v += __shfl_xor_sync(0xffffffffu, v, off);
        if (lane == 0) {
            g_e[edge * HEADS + h] = v;
            atomicMax(&g_menc[d * HEADS + h], fenc(v));
        }
    }
}

__global__ void decode_m_kernel() {
    int tid = blockIdx.x * blockDim.x + threadIdx.x;
    if (tid < NN * HEADS) g_m[tid] = fdec(g_menc[tid]);
}

// ---------------- edge stage 2: exp + segment sum --------------------------
__global__ void edge_p_kernel(const int* __restrict__ ei) {
    int tid = blockIdx.x * blockDim.x + threadIdx.x;
    if (tid >= ET * HEADS) return;
    int edge = tid >> 2;
    int h = tid & 3;
    int s, d;
    edge_sd(ei, edge, s, d);
    float p = __expf(g_e[tid] - g_m[d * HEADS + h]);
    g_e[tid] = p;
    atomicAdd(&g_s[d * HEADS + h], p);
}

// ---------------- edge stage 3: weighted message aggregation ---------------
__global__ void edge_agg_kernel(const int* __restrict__ ei) {
    int edge = blockIdx.x * 8 + (threadIdx.x >> 5);
    if (edge >= ET) return;
    int lane = threadIdx.x & 31;
    int s, d;
    edge_sd(ei, edge, s, d);
    const float* xlp = g_xl + s * CH;
    float* op = g_agg + d * CH;
#pragma unroll
    for (int h = 0; h < HEADS; h++) {
        float alpha = g_e[edge * HEADS + h] / g_s[d * HEADS + h];
        int base = h * HID;
        atomicAdd(&op[base + lane], alpha * xlp[base + lane]);
        atomicAdd(&op[base + lane + 32], alpha * xlp[base + lane + 32]);
    }
}

// ---------------- head mean (last layer, concat=False) ---------------------
__global__ void headmean_kernel() {
    int tid = blockIdx.x * blockDim.x + threadIdx.x;
    if (tid >= NN * HID) return;
    int n = tid >> 6;
    int c = tid & 63;
    const float* a = g_agg + n * CH;
    g_xr[tid] = 0.25f * (a[c] + a[HID + c] + a[2 * HID + c] + a[3 * HID + c]);
}

// ---------------- batch norm (train stats) + ELU ---------------------------
__global__ void bn_stats_kernel(int sel) {
    int C = sel ? HID : CH;
    const float* X = sel ? g_xr : g_agg;
    int ch = threadIdx.x;                      // blockDim.x == C
    float s = 0.f, q = 0.f;
    for (int r = blockIdx.x; r < NN; r += gridDim.x) {
        float v = X[r * C + ch];
        s += v;
        q += v * v;
    }
    atomicAdd(&g_bnsum[ch], (double)s);
    atomicAdd(&g_bnsq[ch], (double)q);
}

__global__ void bn_apply_kernel(const float* __restrict__ gam,
                                const float* __restrict__ bet, int sel) {
    int C = sel ? HID : CH;
    const float* X = sel ? g_xr : g_agg;
    int tid = blockIdx.x * blockDim.x + threadIdx.x;
    if (tid >= NN * C) return;
    int ch = tid & (C - 1);
    float mu = (float)(g_bnsum[ch] * (1.0 / NN));
    float var = (float)(g_bnsq[ch] * (1.0 / NN)) - mu * mu;
    float y = gam[ch] * (X[tid] - mu) * rsqrtf(var + EPS) + bet[ch];
    g_h[tid] = y > 0.f ? y : expm1f(y);        // ELU
}

// ---------------- pooling + MLP head ---------------------------------------
__global__ void pool_sum_kernel(const int* __restrict__ batch) {
    int tid = blockIdx.x * blockDim.x + threadIdx.x;
    if (tid >= NN * HID) return;
    int n = tid >> 6;
    int c = tid & 63;
    atomicAdd(&g_pool[batch[n] * HID + c], g_h[tid]);
}
__global__ void pool_cnt_kernel(const int* __restrict__ batch) {
    int tid = blockIdx.x * blockDim.x + threadIdx.x;
    if (tid >= NN) return;
    atomicAdd(&g_cnt[batch[tid]], 1.f);
}

__global__ void head_kernel(const float* __restrict__ fc1w,
                            const float* __restrict__ fc1b,
                            const float* __restrict__ fc2w,
                            const float* __restrict__ fc2b,
                            float* __restrict__ out) {
    __shared__ float p[HID], h1[HID];
    int g = blockIdx.x, t = threadIdx.x;
    float cnt = fmaxf(g_cnt[g], 1.f);
    p[t] = g_pool[g * HID + t] / cnt;
    __syncthreads();
    float a = fc1b[t];
#pragma unroll
    for (int k = 0; k < HID; k++) a += p[k] * fc1w[k * HID + t];
    h1[t] = fmaxf(a, 0.f);
    __syncthreads();
    if (t < NC) {
        float o = fc2b[t];
#pragma unroll
        for (int k = 0; k < HID; k++) o += h1[k] * fc2w[k * NC + t];
        out[g * NC + t] = o;
    }
}

// ---------------- launcher -------------------------------------------------
static inline int cdiv(int a, int b) { return (a + b - 1) / b; }

extern "C" void kernel_launch(void* const* d_in, const int* in_sizes, int n_in,
                              void* d_out, int out_size) {
    const float* x = (const float*)d_in[0];
    const int* ei = (const int*)d_in[1];
    const int* batch = (const int*)d_in[2];
    const float *Wl[4], *Wr[4], *att[4], *gam[4], *bet[4];
    for (int i = 0; i < 4; i++) {
        Wl[i] = (const float*)d_in[3 + 6 * i];
        Wr[i] = (const float*)d_in[4 + 6 * i];
        att[i] = (const float*)d_in[5 + 6 * i];
        // d_in[6+6i] is bias b_i — provably cancels inside train-mode BN, skip
        gam[i] = (const float*)d_in[7 + 6 * i];
        bet[i] = (const float*)d_in[8 + 6 * i];
    }
    const float* fc1w = (const float*)d_in[27];
    const float* fc1b = (const float*)d_in[28];
    const float* fc2w = (const float*)d_in[29];
    const float* fc2b = (const float*)d_in[30];
    float* out = (float*)d_out;

    dim3 ggrid(CH / BN, cdiv(NN, BM));

    for (int i = 0; i < 4; i++) {
        int K = (i == 0) ? IN_DIM : CH;
        int a_sel = (i == 0) ? 0 : 1;
        gemm_kernel<<<ggrid, 256>>>(x, Wl[i], K, a_sel, 0);
        gemm_kernel<<<ggrid, 256>>>(x, Wr[i], K, a_sel, 1);

        clear_edge_kernel<<<cdiv(NN * CH, 256), 256>>>();
        edge_e_kernel<<<cdiv(ET, 8), 256>>>(ei, att[i]);
        decode_m_kernel<<<cdiv(NN * HEADS, 256), 256>>>();
        edge_p_kernel<<<cdiv(ET * HEADS, 256), 256>>>(ei);
        edge_agg_kernel<<<cdiv(ET, 8), 256>>>(ei);

        if (i < 3) {
            clear_bn_kernel<<<1, 256>>>();
            bn_stats_kernel<<<256, CH>>>(0);
            bn_apply_kernel<<<cdiv(NN * CH, 256), 256>>>(gam[i], bet[i], 0);
        } else {
            headmean_kernel<<<cdiv(NN * HID, 256), 256>>>();
            clear_bn_kernel<<<1, 256>>>();
            bn_stats_kernel<<<256, HID>>>(1);
            bn_apply_kernel<<<cdiv(NN * HID, 256), 256>>>(gam[i], bet[i], 1);
        }
    }

    clear_pool_kernel<<<cdiv(GG * HID, 256), 256>>>();
    pool_sum_kernel<<<cdiv(NN * HID, 256), 256>>>(batch);
    pool_cnt_kernel<<<cdiv(NN, 256), 256>>>(batch);
    head_kernel<<<GG, HID>>>(fc1w, fc1b, fc2w, fc2b, out);
}

// round 4
// speedup vs baseline: 2.0485x; 2.0485x over previous
#include <cuda_runtime.h>
#include <cuda_bf16.h>
#include <math_constants.h>

#define NN 30000
#define EE 300000
#define GG 128
#define IN_DIM 128
#define HID 64
#define HEADS 4
#define CH 256            // HEADS*HID
#define NC 10
#define EPS 1e-5f
#define SLOPE 0.2f

// ---------------- scratch (device globals; no allocation allowed) ----------
__device__ float g_xl[NN * CH];
__device__ float g_xr[NN * CH];
__device__ float g_h[NN * CH];
__device__ float g_agg[NN * CH];
__device__ int   g_deg[NN];
__device__ int   g_off[NN + 1];
__device__ int   g_cur[NN];
__device__ int   g_csr[EE];
__device__ double g_bnsum[CH];
__device__ double g_bnsq[CH];
__device__ float g_pool[GG * HID];
__device__ float g_cnt[GG];

// ---------------- CSR build -------------------------------------------------
__global__ void deg_clear_kernel() {
    int tid = blockIdx.x * blockDim.x + threadIdx.x;
    if (tid < NN) g_deg[tid] = 0;
}
__global__ void deg_count_kernel(const int* __restrict__ ei) {
    int e = blockIdx.x * blockDim.x + threadIdx.x;
    if (e < EE) atomicAdd(&g_deg[ei[EE + e]], 1);
}
__global__ void scan_kernel() {      // single block, 1024 threads
    __shared__ int warp_sums[32];
    int t = threadIdx.x;
    int lane = t & 31, wid = t >> 5;
    int carry = 0;
    if (t == 0) g_off[0] = 0;
    for (int base = 0; base < NN; base += 1024) {
        int i = base + t;
        int v = (i < NN) ? g_deg[i] : 0;
        int x = v;
#pragma unroll
        for (int off = 1; off < 32; off <<= 1) {
            int y = __shfl_up_sync(0xffffffffu, x, off);
            if (lane >= off) x += y;
        }
        if (lane == 31) warp_sums[wid] = x;
        __syncthreads();
        if (wid == 0) {
            int w = warp_sums[lane];
#pragma unroll
            for (int off = 1; off < 32; off <<= 1) {
                int y = __shfl_up_sync(0xffffffffu, w, off);
                if (lane >= off) w += y;
            }
            warp_sums[lane] = w;
        }
        __syncthreads();
        int incl = x + (wid ? warp_sums[wid - 1] : 0) + carry;
        if (i < NN) { g_off[i + 1] = incl; g_cur[i] = incl - v; }
        carry += warp_sums[31];
        __syncthreads();   // protect warp_sums before next chunk overwrites
    }
}
__global__ void scatter_kernel(const int* __restrict__ ei) {
    int e = blockIdx.x * blockDim.x + threadIdx.x;
    if (e < EE) {
        int s = ei[e], d = ei[EE + e];
        int p = atomicAdd(&g_cur[d], 1);
        g_csr[p] = s;
    }
}

// ---------------- GEMM: C[N x 256] = A[N x K] @ W[K x 256] ------------------
// 128x64 tile, 256 threads, 8x4 micro-tile, grid.z selects Wl/Wr output.
#define BM 128
#define BN 64
#define BK 16
__global__ void gemm_kernel(const float* __restrict__ xin,
                            const float* __restrict__ W0,
                            const float* __restrict__ W1,
                            int K, int a_sel) {
    __shared__ float As[BK][BM];       // transposed A tile
    __shared__ float Bs[BK][BN + 4];
    const float* A = a_sel ? g_h : xin;
    const float* W = blockIdx.z ? W1 : W0;
    float* C = blockIdx.z ? g_xr : g_xl;

    int bm = blockIdx.y * BM;
    int bn = blockIdx.x * BN;
    int tx = threadIdx.x & 15;         // 16 groups of 4 cols
    int ty = threadIdx.x >> 4;         // 16 groups of 8 rows

    float acc[8][4];
#pragma unroll
    for (int i = 0; i < 8; i++)
#pragma unroll
        for (int j = 0; j < 4; j++) acc[i][j] = 0.f;

    for (int k0 = 0; k0 < K; k0 += BK) {
        // A tile: 128 rows x 16 k, float4 along K (coalesced), store transposed
#pragma unroll
        for (int f = threadIdx.x; f < BM * BK / 4; f += 256) {
            int m = f >> 2;
            int k4 = (f & 3) * 4;
            int row = bm + m;
            float4 v = (row < NN) ? *(const float4*)(A + row * K + k0 + k4)
                                  : make_float4(0.f, 0.f, 0.f, 0.f);
            As[k4 + 0][m] = v.x; As[k4 + 1][m] = v.y;
            As[k4 + 2][m] = v.z; As[k4 + 3][m] = v.w;
        }
        // B tile: 16 k x 64 cols, one float4 per thread
        {
            int f = threadIdx.x;
            int kk = f >> 4;
            int n4 = (f & 15) * 4;
            float4 v = *(const float4*)(W + (k0 + kk) * CH + bn + n4);
            *(float4*)(&Bs[kk][n4]) = v;
        }
        __syncthreads();
#pragma unroll
        for (int kk = 0; kk < BK; kk++) {
            float ra[8], rb[4];
            *(float4*)(ra)     = *(const float4*)(&As[kk][ty * 8]);
            *(float4*)(ra + 4) = *(const float4*)(&As[kk][ty * 8 + 4]);
            *(float4*)(rb)     = *(const float4*)(&Bs[kk][tx * 4]);
#pragma unroll
            for (int i = 0; i < 8; i++)
#pragma unroll
                for (int j = 0; j < 4; j++) acc[i][j] += ra[i] * rb[j];
        }
        __syncthreads();
    }
#pragma unroll
    for (int i = 0; i < 8; i++) {
        int row = bm + ty * 8 + i;
        if (row < NN) {
            *(float4*)(C + row * CH + bn + tx * 4) =
                make_float4(acc[i][0], acc[i][1], acc[i][2], acc[i][3]);
        }
    }
}

// ---------------- fused GATv2 aggregation: warp per dst node ----------------
// lane holds channels [lane*8, lane*8+8); head = lane>>3 (8 lanes per head).
// Online softmax over self-loop + CSR incoming edges; no atomics anywhere.
__global__ void gat_kernel(const float* __restrict__ att) {
    int node = blockIdx.x * 8 + (threadIdx.x >> 5);
    if (node >= NN) return;
    int lane = threadIdx.x & 31;
    int cbase = lane * 8;

    float4 at0 = *(const float4*)(att + cbase);
    float4 at1 = *(const float4*)(att + cbase + 4);
    const float4* xrp = (const float4*)(g_xr + node * CH + cbase);
    float4 xr0 = xrp[0], xr1 = xrp[1];

    float m = -CUDART_INF_F, s = 0.f;
    float acc[8];
#pragma unroll
    for (int j = 0; j < 8; j++) acc[j] = 0.f;

    int start = g_off[node], end = g_off[node + 1];
    for (int idx = start - 1; idx < end; idx++) {
        int src = (idx < start) ? node : g_csr[idx];
        const float4* xlp = (const float4*)(g_xl + src * CH + cbase);
        float4 xl0 = xlp[0], xl1 = xlp[1];

        float e;
        {
            float q, t = 0.f;
            q = xl0.x + xr0.x; q = q > 0.f ? q : SLOPE * q; t += q * at0.x;
            q = xl0.y + xr0.y; q = q > 0.f ? q : SLOPE * q; t += q * at0.y;
            q = xl0.z + xr0.z; q = q > 0.f ? q : SLOPE * q; t += q * at0.z;
            q = xl0.w + xr0.w; q = q > 0.f ? q : SLOPE * q; t += q * at0.w;
            q = xl1.x + xr1.x; q = q > 0.f ? q : SLOPE * q; t += q * at1.x;
            q = xl1.y + xr1.y; q = q > 0.f ? q : SLOPE * q; t += q * at1.y;
            q = xl1.z + xr1.z; q = q > 0.f ? q : SLOPE * q; t += q * at1.z;
            q = xl1.w + xr1.w; q = q > 0.f ? q : SLOPE * q; t += q * at1.w;
            e = t;
        }
        // reduce across the 8 lanes of this head
        e += __shfl_xor_sync(0xffffffffu, e, 1);
        e += __shfl_xor_sync(0xffffffffu, e, 2);
        e += __shfl_xor_sync(0xffffffffu, e, 4);

        float mnew = fmaxf(m, e);
        float c = __expf(m - mnew);     // 0 on first iteration (m = -inf)
        float p = __expf(e - mnew);
        s = s * c + p;
        acc[0] = acc[0] * c + p * xl0.x;
        acc[1] = acc[1] * c + p * xl0.y;
        acc[2] = acc[2] * c + p * xl0.z;
        acc[3] = acc[3] * c + p * xl0.w;
        acc[4] = acc[4] * c + p * xl1.x;
        acc[5] = acc[5] * c + p * xl1.y;
        acc[6] = acc[6] * c + p * xl1.z;
        acc[7] = acc[7] * c + p * xl1.w;
        m = mnew;
    }
    float inv = 1.f / s;
    float4* op = (float4*)(g_agg + node * CH + cbase);
    op[0] = make_float4(acc[0] * inv, acc[1] * inv, acc[2] * inv, acc[3] * inv);
    op[1] = make_float4(acc[4] * inv, acc[5] * inv, acc[6] * inv, acc[7] * inv);
}

// ---------------- head mean (last layer, concat=False) ----------------------
__global__ void headmean_kernel() {
    int tid = blockIdx.x * blockDim.x + threadIdx.x;
    if (tid >= NN * HID) return;
    int n = tid >> 6;
    int c = tid & 63;
    const float* a = g_agg + n * CH;
    g_xr[tid] = 0.25f * (a[c] + a[HID + c] + a[2 * HID + c] + a[3 * HID + c]);
}

// ---------------- batch norm (train stats) + ELU ----------------------------
__global__ void clear_bn_kernel() {
    int t = threadIdx.x;
    if (t < CH) { g_bnsum[t] = 0.0; g_bnsq[t] = 0.0; }
}
__global__ void bn_stats_kernel(int sel) {
    int C = sel ? HID : CH;
    const float* X = sel ? g_xr : g_agg;
    int ch = threadIdx.x;                      // blockDim.x == C
    float s = 0.f, q = 0.f;
    for (int r = blockIdx.x; r < NN; r += gridDim.x) {
        float v = X[r * C + ch];
        s += v;
        q += v * v;
    }
    atomicAdd(&g_bnsum[ch], (double)s);
    atomicAdd(&g_bnsq[ch], (double)q);
}
__global__ void bn_apply_kernel(const float* __restrict__ gam,
                                const float* __restrict__ bet, int sel) {
    int C = sel ? HID : CH;
    const float* X = sel ? g_xr : g_agg;
    int tid = blockIdx.x * blockDim.x + threadIdx.x;
    if (tid >= NN * C) return;
    int ch = tid & (C - 1);
    float mu = (float)(g_bnsum[ch] * (1.0 / NN));
    float var = (float)(g_bnsq[ch] * (1.0 / NN)) - mu * mu;
    float y = gam[ch] * (X[tid] - mu) * rsqrtf(var + EPS) + bet[ch];
    g_h[tid] = y > 0.f ? y : expm1f(y);        // ELU
}

// ---------------- pooling + MLP head ----------------------------------------
__global__ void clear_pool_kernel() {
    int tid = blockIdx.x * blockDim.x + threadIdx.x;
    if (tid < GG * HID) g_pool[tid] = 0.f;
    if (tid < GG) g_cnt[tid] = 0.f;
}
__global__ void pool_sum_kernel(const int* __restrict__ batch) {
    int tid = blockIdx.x * blockDim.x + threadIdx.x;
    if (tid >= NN * HID) return;
    int n = tid >> 6;
    int c = tid & 63;
    atomicAdd(&g_pool[batch[n] * HID + c], g_h[tid]);
}
__global__ void pool_cnt_kernel(const int* __restrict__ batch) {
    int tid = blockIdx.x * blockDim.x + threadIdx.x;
    if (tid >= NN) return;
    atomicAdd(&g_cnt[batch[tid]], 1.f);
}
__global__ void head_kernel(const float* __restrict__ fc1w,
                            const float* __restrict__ fc1b,
                            const float* __restrict__ fc2w,
                            const float* __restrict__ fc2b,
                            float* __restrict__ out) {
    __shared__ float p[HID], h1[HID];
    int g = blockIdx.x, t = threadIdx.x;
    float cnt = fmaxf(g_cnt[g], 1.f);
    p[t] = g_pool[g * HID + t] / cnt;
    __syncthreads();
    float a = fc1b[t];
#pragma unroll
    for (int k = 0; k < HID; k++) a += p[k] * fc1w[k * HID + t];
    h1[t] = fmaxf(a, 0.f);
    __syncthreads();
    if (t < NC) {
        float o = fc2b[t];
#pragma unroll
        for (int k = 0; k < HID; k++) o += h1[k] * fc2w[k * NC + t];
        out[g * NC + t] = o;
    }
}

// ---------------- launcher ---------------------------------------------------
static inline int cdiv(int a, int b) { return (a + b - 1) / b; }

extern "C" void kernel_launch(void* const* d_in, const int* in_sizes, int n_in,
                              void* d_out, int out_size) {
    const float* x = (const float*)d_in[0];
    const int* ei = (const int*)d_in[1];
    const int* batch = (const int*)d_in[2];
    const float *Wl[4], *Wr[4], *att[4], *gam[4], *bet[4];
    for (int i = 0; i < 4; i++) {
        Wl[i] = (const float*)d_in[3 + 6 * i];
        Wr[i] = (const float*)d_in[4 + 6 * i];
        att[i] = (const float*)d_in[5 + 6 * i];
        // d_in[6+6i] is bias b_i — cancels inside train-mode BN, skipped
        gam[i] = (const float*)d_in[7 + 6 * i];
        bet[i] = (const float*)d_in[8 + 6 * i];
    }
    const float* fc1w = (const float*)d_in[27];
    const float* fc1b = (const float*)d_in[28];
    const float* fc2w = (const float*)d_in[29];
    const float* fc2b = (const float*)d_in[30];
    float* out = (float*)d_out;

    // ---- build CSR once per call (edge_index is the same for all layers)
    deg_clear_kernel<<<cdiv(NN, 256), 256>>>();
    deg_count_kernel<<<cdiv(EE, 256), 256>>>(ei);
    scan_kernel<<<1, 1024>>>();
    scatter_kernel<<<cdiv(EE, 256), 256>>>(ei);

    dim3 ggrid(CH / BN, cdiv(NN, BM), 2);

    for (int i = 0; i < 4; i++) {
        int K = (i == 0) ? IN_DIM : CH;
        int a_sel = (i == 0) ? 0 : 1;
        gemm_kernel<<<ggrid, 256>>>(x, Wl[i], Wr[i], K, a_sel);

        gat_kernel<<<cdiv(NN, 8), 256>>>(att[i]);

        if (i < 3) {
            clear_bn_kernel<<<1, 256>>>();
            bn_stats_kernel<<<256, CH>>>(0);
            bn_apply_kernel<<<cdiv(NN * CH, 256), 256>>>(gam[i], bet[i], 0);
        } else {
            headmean_kernel<<<cdiv(NN * HID, 256), 256>>>();
            clear_bn_kernel<<<1, 256>>>();
            bn_stats_kernel<<<256, HID>>>(1);
            bn_apply_kernel<<<cdiv(NN * HID, 256), 256>>>(gam[i], bet[i], 1);
        }
    }

    clear_pool_kernel<<<cdiv(GG * HID, 256), 256>>>();
    pool_sum_kernel<<<cdiv(NN * HID, 256), 256>>>(batch);
    pool_cnt_kernel<<<cdiv(NN, 256), 256>>>(batch);
    head_kernel<<<GG, HID>>>(fc1w, fc1b, fc2w, fc2b, out);
}

// round 6
// speedup vs baseline: 2.1483x; 1.0487x over previous
#include <cuda_runtime.h>
#include <cuda_bf16.h>
#include <math_constants.h>

#define NN 30000
#define EE 300000
#define GG 128
#define IN_DIM 128
#define HID 64
#define HEADS 4
#define CH 256            // HEADS*HID
#define NC 10
#define EPS 1e-5f
#define SLOPE 0.2f

typedef unsigned long long u64;

// ---------------- scratch (device globals; no allocation allowed) ----------
__device__ float g_xl[NN * CH];
__device__ float g_xr[NN * CH];
__device__ float g_h[NN * CH];
__device__ float g_agg[NN * CH];
__device__ int   g_deg[NN];
__device__ int   g_off[NN + 1];
__device__ int   g_cur[NN];
__device__ int   g_csr[EE];
__device__ double g_bnsum[CH];
__device__ double g_bnsq[CH];
__device__ float g_pool[GG * HID];
__device__ float g_cnt[GG];

// ---------------- packed f32x2 helpers --------------------------------------
__device__ __forceinline__ void fma2(u64& d, u64 a, u64 b) {
    asm("fma.rn.f32x2 %0, %1, %2, %0;" : "+l"(d) : "l"(a), "l"(b));
}
__device__ __forceinline__ u64 dup2(float x) {
    u64 r;
    asm("mov.b64 %0, {%1, %1};" : "=l"(r) : "f"(x));
    return r;
}
__device__ __forceinline__ void unpack2(u64 v, float& lo, float& hi) {
    asm("mov.b64 {%0, %1}, %2;" : "=f"(lo), "=f"(hi) : "l"(v));
}

// ---------------- CSR build -------------------------------------------------
__global__ void deg_clear_kernel() {
    int tid = blockIdx.x * blockDim.x + threadIdx.x;
    if (tid < NN) g_deg[tid] = 0;
}
__global__ void deg_count_kernel(const int* __restrict__ ei) {
    int e = blockIdx.x * blockDim.x + threadIdx.x;
    if (e < EE) atomicAdd(&g_deg[ei[EE + e]], 1);
}
__global__ void scan_kernel() {      // single block, 1024 threads
    __shared__ int warp_sums[32];
    int t = threadIdx.x;
    int lane = t & 31, wid = t >> 5;
    int carry = 0;
    if (t == 0) g_off[0] = 0;
    for (int base = 0; base < NN; base += 1024) {
        int i = base + t;
        int v = (i < NN) ? g_deg[i] : 0;
        int x = v;
#pragma unroll
        for (int off = 1; off < 32; off <<= 1) {
            int y = __shfl_up_sync(0xffffffffu, x, off);
            if (lane >= off) x += y;
        }
        if (lane == 31) warp_sums[wid] = x;
        __syncthreads();
        if (wid == 0) {
            int w = warp_sums[lane];
#pragma unroll
            for (int off = 1; off < 32; off <<= 1) {
                int y = __shfl_up_sync(0xffffffffu, w, off);
                if (lane >= off) w += y;
            }
            warp_sums[lane] = w;
        }
        __syncthreads();
        int incl = x + (wid ? warp_sums[wid - 1] : 0) + carry;
        if (i < NN) { g_off[i + 1] = incl; g_cur[i] = incl - v; }
        carry += warp_sums[31];
        __syncthreads();
    }
}
__global__ void scatter_kernel(const int* __restrict__ ei) {
    int e = blockIdx.x * blockDim.x + threadIdx.x;
    if (e < EE) {
        int s = ei[e], d = ei[EE + e];
        int p = atomicAdd(&g_cur[d], 1);
        g_csr[p] = s;
    }
}

// ---------------- GEMM: C[N x 256] = A[N x K] @ W[K x 256] ------------------
// 128x64 tile, 256 threads. Micro-tile 8x4 organized as 4 row-pairs x 4 cols,
// accumulated with packed fma.rn.f32x2 (FFMA2): row-pairs load straight from
// the transposed A tile as LDS.64; B columns duplicated via mov.b64.
#define BM 128
#define BN 64
#define BK 16
__global__ void gemm_kernel(const float* __restrict__ xin,
                            const float* __restrict__ W0,
                            const float* __restrict__ W1,
                            int K, int a_sel) {
    __shared__ float As[BK][BM];       // transposed A tile
    __shared__ float Bs[BK][BN + 4];
    const float* A = a_sel ? g_h : xin;
    const float* W = blockIdx.z ? W1 : W0;
    float* C = blockIdx.z ? g_xr : g_xl;

    int bm = blockIdx.y * BM;
    int bn = blockIdx.x * BN;
    int tx = threadIdx.x & 15;         // 16 groups of 4 cols
    int ty = threadIdx.x >> 4;         // 16 groups of 8 rows (4 row-pairs)

    u64 acc[4][4];                     // [row-pair][col], each = (row2i, row2i+1)
#pragma unroll
    for (int i = 0; i < 4; i++)
#pragma unroll
        for (int j = 0; j < 4; j++) acc[i][j] = 0ull;

    for (int k0 = 0; k0 < K; k0 += BK) {
        // A tile: 128 rows x 16 k, float4 along K (coalesced), store transposed
#pragma unroll
        for (int f = threadIdx.x; f < BM * BK / 4; f += 256) {
            int m = f >> 2;
            int k4 = (f & 3) * 4;
            int row = bm + m;
            float4 v = (row < NN) ? *(const float4*)(A + row * K + k0 + k4)
                                  : make_float4(0.f, 0.f, 0.f, 0.f);
            As[k4 + 0][m] = v.x; As[k4 + 1][m] = v.y;
            As[k4 + 2][m] = v.z; As[k4 + 3][m] = v.w;
        }
        // B tile: 16 k x 64 cols, one float4 per thread
        {
            int f = threadIdx.x;
            int kk = f >> 4;
            int n4 = (f & 15) * 4;
            float4 v = *(const float4*)(W + (k0 + kk) * CH + bn + n4);
            *(float4*)(&Bs[kk][n4]) = v;
        }
        __syncthreads();
#pragma unroll
        for (int kk = 0; kk < BK; kk++) {
            u64 ra[4];
#pragma unroll
            for (int i = 0; i < 4; i++)
                ra[i] = *(const u64*)(&As[kk][ty * 8 + 2 * i]);
            float4 b4 = *(const float4*)(&Bs[kk][tx * 4]);
            u64 rb[4];
            rb[0] = dup2(b4.x); rb[1] = dup2(b4.y);
            rb[2] = dup2(b4.z); rb[3] = dup2(b4.w);
#pragma unroll
            for (int i = 0; i < 4; i++)
#pragma unroll
                for (int j = 0; j < 4; j++)
                    fma2(acc[i][j], ra[i], rb[j]);
        }
        __syncthreads();
    }
#pragma unroll
    for (int i = 0; i < 4; i++) {
        float lo[4], hi[4];
#pragma unroll
        for (int j = 0; j < 4; j++) unpack2(acc[i][j], lo[j], hi[j]);
        int row0 = bm + ty * 8 + 2 * i;
        if (row0 < NN)
            *(float4*)(C + row0 * CH + bn + tx * 4) =
                make_float4(lo[0], lo[1], lo[2], lo[3]);
        if (row0 + 1 < NN)
            *(float4*)(C + (row0 + 1) * CH + bn + tx * 4) =
                make_float4(hi[0], hi[1], hi[2], hi[3]);
    }
}

// ---------------- fused GATv2 aggregation: warp per dst node ----------------
__global__ void gat_kernel(const float* __restrict__ att) {
    int node = blockIdx.x * 8 + (threadIdx.x >> 5);
    if (node >= NN) return;
    int lane = threadIdx.x & 31;
    int cbase = lane * 8;

    float4 at0 = *(const float4*)(att + cbase);
    float4 at1 = *(const float4*)(att + cbase + 4);
    const float4* xrp = (const float4*)(g_xr + node * CH + cbase);
    float4 xr0 = xrp[0], xr1 = xrp[1];

    float m = -CUDART_INF_F, s = 0.f;
    float acc[8];
#pragma unroll
    for (int j = 0; j < 8; j++) acc[j] = 0.f;

    int start = g_off[node], end = g_off[node + 1];
    for (int idx = start - 1; idx < end; idx++) {
        int src = (idx < start) ? node : g_csr[idx];
        const float4* xlp = (const float4*)(g_xl + src * CH + cbase);
        float4 xl0 = xlp[0], xl1 = xlp[1];

        float e;
        {
            float q, t = 0.f;
            q = xl0.x + xr0.x; q = q > 0.f ? q : SLOPE * q; t += q * at0.x;
            q = xl0.y + xr0.y; q = q > 0.f ? q : SLOPE * q; t += q * at0.y;
            q = xl0.z + xr0.z; q = q > 0.f ? q : SLOPE * q; t += q * at0.z;
            q = xl0.w + xr0.w; q = q > 0.f ? q : SLOPE * q; t += q * at0.w;
            q = xl1.x + xr1.x; q = q > 0.f ? q : SLOPE * q; t += q * at1.x;
            q = xl1.y + xr1.y; q = q > 0.f ? q : SLOPE * q; t += q * at1.y;
            q = xl1.z + xr1.z; q = q > 0.f ? q : SLOPE * q; t += q * at1.z;
            q = xl1.w + xr1.w; q = q > 0.f ? q : SLOPE * q; t += q * at1.w;
            e = t;
        }
        e += __shfl_xor_sync(0xffffffffu, e, 1);
        e += __shfl_xor_sync(0xffffffffu, e, 2);
        e += __shfl_xor_sync(0xffffffffu, e, 4);

        float mnew = fmaxf(m, e);
        float c = __expf(m - mnew);
        float p = __expf(e - mnew);
        s = s * c + p;
        acc[0] = acc[0] * c + p * xl0.x;
        acc[1] = acc[1] * c + p * xl0.y;
        acc[2] = acc[2] * c + p * xl0.z;
        acc[3] = acc[3] * c + p * xl0.w;
        acc[4] = acc[4] * c + p * xl1.x;
        acc[5] = acc[5] * c + p * xl1.y;
        acc[6] = acc[6] * c + p * xl1.z;
        acc[7] = acc[7] * c + p * xl1.w;
        m = mnew;
    }
    float inv = 1.f / s;
    float4* op = (float4*)(g_agg + node * CH + cbase);
    op[0] = make_float4(acc[0] * inv, acc[1] * inv, acc[2] * inv, acc[3] * inv);
    op[1] = make_float4(acc[4] * inv, acc[5] * inv, acc[6] * inv, acc[7] * inv);
}

// ---------------- head mean (last layer, concat=False) ----------------------
__global__ void headmean_kernel() {
    int tid = blockIdx.x * blockDim.x + threadIdx.x;
    if (tid >= NN * HID) return;
    int n = tid >> 6;
    int c = tid & 63;
    const float* a = g_agg + n * CH;
    g_xr[tid] = 0.25f * (a[c] + a[HID + c] + a[2 * HID + c] + a[3 * HID + c]);
}

// ---------------- batch norm (train stats) + ELU ----------------------------
__global__ void clear_bn_kernel() {
    int t = threadIdx.x;
    if (t < CH) { g_bnsum[t] = 0.0; g_bnsq[t] = 0.0; }
}
__global__ void bn_stats_kernel(int sel) {
    int C = sel ? HID : CH;
    const float* X = sel ? g_xr : g_agg;
    int ch = threadIdx.x;
    float s = 0.f, q = 0.f;
    for (int r = blockIdx.x; r < NN; r += gridDim.x) {
        float v = X[r * C + ch];
        s += v;
        q += v * v;
    }
    atomicAdd(&g_bnsum[ch], (double)s);
    atomicAdd(&g_bnsq[ch], (double)q);
}
__global__ void bn_apply_kernel(const float* __restrict__ gam,
                                const float* __restrict__ bet, int sel) {
    int C = sel ? HID : CH;
    const float* X = sel ? g_xr : g_agg;
    int tid = blockIdx.x * blockDim.x + threadIdx.x;
    if (tid >= NN * C) return;
    int ch = tid & (C - 1);
    float mu = (float)(g_bnsum[ch] * (1.0 / NN));
    float var = (float)(g_bnsq[ch] * (1.0 / NN)) - mu * mu;
    float y = gam[ch] * (X[tid] - mu) * rsqrtf(var + EPS) + bet[ch];
    g_h[tid] = y > 0.f ? y : expm1f(y);        // ELU
}

// ---------------- pooling + MLP head ----------------------------------------
__global__ void clear_pool_kernel() {
    int tid = blockIdx.x * blockDim.x + threadIdx.x;
    if (tid < GG * HID) g_pool[tid] = 0.f;
    if (tid < GG) g_cnt[tid] = 0.f;
}
__global__ void pool_sum_kernel(const int* __restrict__ batch) {
    int tid = blockIdx.x * blockDim.x + threadIdx.x;
    if (tid >= NN * HID) return;
    int n = tid >> 6;
    int c = tid & 63;
    atomicAdd(&g_pool[batch[n] * HID + c], g_h[tid]);
}
__global__ void pool_cnt_kernel(const int* __restrict__ batch) {
    int tid = blockIdx.x * blockDim.x + threadIdx.x;
    if (tid >= NN) return;
    atomicAdd(&g_cnt[batch[tid]], 1.f);
}
__global__ void head_kernel(const float* __restrict__ fc1w,
                            const float* __restrict__ fc1b,
                            const float* __restrict__ fc2w,
                            const float* __restrict__ fc2b,
                            float* __restrict__ out) {
    __shared__ float p[HID], h1[HID];
    int g = blockIdx.x, t = threadIdx.x;
    float cnt = fmaxf(g_cnt[g], 1.f);
    p[t] = g_pool[g * HID + t] / cnt;
    __syncthreads();
    float a = fc1b[t];
#pragma unroll
    for (int k = 0; k < HID; k++) a += p[k] * fc1w[k * HID + t];
    h1[t] = fmaxf(a, 0.f);
    __syncthreads();
    if (t < NC) {
        float o = fc2b[t];
#pragma unroll
        for (int k = 0; k < HID; k++) o += h1[k] * fc2w[k * NC + t];
        out[g * NC + t] = o;
    }
}

// ---------------- launcher ---------------------------------------------------
static inline int cdiv(int a, int b) { return (a + b - 1) / b; }

extern "C" void kernel_launch(void* const* d_in, const int* in_sizes, int n_in,
                              void* d_out, int out_size) {
    const float* x = (const float*)d_in[0];
    const int* ei = (const int*)d_in[1];
    const int* batch = (const int*)d_in[2];
    const float *Wl[4], *Wr[4], *att[4], *gam[4], *bet[4];
    for (int i = 0; i < 4; i++) {
        Wl[i] = (const float*)d_in[3 + 6 * i];
        Wr[i] = (const float*)d_in[4 + 6 * i];
        att[i] = (const float*)d_in[5 + 6 * i];
        gam[i] = (const float*)d_in[7 + 6 * i];
        bet[i] = (const float*)d_in[8 + 6 * i];
    }
    const float* fc1w = (const float*)d_in[27];
    const float* fc1b = (const float*)d_in[28];
    const float* fc2w = (const float*)d_in[29];
    const float* fc2b = (const float*)d_in[30];
    float* out = (float*)d_out;

    // ---- build CSR once per call (edge_index is the same for all layers)
    deg_clear_kernel<<<cdiv(NN, 256), 256>>>();
    deg_count_kernel<<<cdiv(EE, 256), 256>>>(ei);
    scan_kernel<<<1, 1024>>>();
    scatter_kernel<<<cdiv(EE, 256), 256>>>(ei);

    dim3 ggrid(CH / BN, cdiv(NN, BM), 2);

    for (int i = 0; i < 4; i++) {
        int K = (i == 0) ? IN_DIM : CH;
        int a_sel = (i == 0) ? 0 : 1;
        gemm_kernel<<<ggrid, 256>>>(x, Wl[i], Wr[i], K, a_sel);

        gat_kernel<<<cdiv(NN, 8), 256>>>(att[i]);

        if (i < 3) {
            clear_bn_kernel<<<1, 256>>>();
            bn_stats_kernel<<<256, CH>>>(0);
            bn_apply_kernel<<<cdiv(NN * CH, 256), 256>>>(gam[i], bet[i], 0);
        } else {
            headmean_kernel<<<cdiv(NN * HID, 256), 256>>>();
            clear_bn_kernel<<<1, 256>>>();
            bn_stats_kernel<<<256, HID>>>(1);
            bn_apply_kernel<<<cdiv(NN * HID, 256), 256>>>(gam[i], bet[i], 1);
        }
    }

    clear_pool_kernel<<<cdiv(GG * HID, 256), 256>>>();
    pool_sum_kernel<<<cdiv(NN * HID, 256), 256>>>(batch);
    pool_cnt_kernel<<<cdiv(NN, 256), 256>>>(batch);
    head_kernel<<<GG, HID>>>(fc1w, fc1b, fc2w, fc2b, out);
}